// round 1
// baseline (speedup 1.0000x reference)
#include <cuda_runtime.h>
#include <math.h>

#define D 128
#define QSPLIT 32

// Static scratch (allocation-free rule: __device__ globals).
__device__ float g_P[4096 * 128];                      // normalized p1 rows [0,B), p2 rows [B,2B)
__device__ float g_NN[4096 * 128];                     // gathered nearest neighbours
__device__ unsigned long long g_part[QSPLIT * 4096];   // partial argmax keys
__device__ int g_idx[4096];
__device__ float g_logits[8192 * 2048];                // [M1; M1^T; M2; M2^T] / T

// ---------------------------------------------------------------------------
// helpers
// ---------------------------------------------------------------------------

__device__ __forceinline__ unsigned ford(float f) {
    unsigned u = __float_as_uint(f);
    return (u & 0x80000000u) ? ~u : (u | 0x80000000u);
}

// Load a 128x128 fp32 tile (row-major, stride 128) into k-major swizzled smem.
// Element (k, r) lives at float index: k*128 + (((r>>2) ^ ((k>>2)&31))<<2) + (r&3).
// Gmem reads: one warp reads one full row (32 consecutive float4s) per step.
__device__ __forceinline__ void load_tile_sw(const float* __restrict__ src,
                                             float* sm, int tid) {
    int w = tid >> 5, l = tid & 31;
#pragma unroll
    for (int m = 0; m < 16; m++) {
        int r = w + m * 8;
        float4 v = *(const float4*)(src + (size_t)r * D + 4 * l);
        int slot = (((r >> 2) ^ l) << 2) + (r & 3);   // (k>>2)&31 == l for k=4l+j
        sm[(4 * l + 0) * 128 + slot] = v.x;
        sm[(4 * l + 1) * 128 + slot] = v.y;
        sm[(4 * l + 2) * 128 + slot] = v.z;
        sm[(4 * l + 3) * 128 + slot] = v.w;
    }
}

// 128x128x128 register-tiled multiply: thread (tx,ty) in a 16x16 grid owns
// rows {4ty..4ty+3, 64+4ty..64+4ty+3} x cols {4tx..4tx+3, 64+4tx..64+4tx+3}.
__device__ __forceinline__ void mm_tile(const float* sp, const float* sq,
                                        int tx, int ty, float c[8][8]) {
    const float4* sp4 = (const float4*)sp;
    const float4* sq4 = (const float4*)sq;
#pragma unroll 4
    for (int k = 0; k < 128; k++) {
        int s = (k >> 2) & 31;
        float4 A0 = sp4[k * 32 + (ty ^ s)];
        float4 A1 = sp4[k * 32 + ((ty + 16) ^ s)];
        float4 B0 = sq4[k * 32 + (tx ^ s)];
        float4 B1 = sq4[k * 32 + ((tx + 16) ^ s)];
        float a[8] = {A0.x, A0.y, A0.z, A0.w, A1.x, A1.y, A1.z, A1.w};
        float b[8] = {B0.x, B0.y, B0.z, B0.w, B1.x, B1.y, B1.z, B1.w};
#pragma unroll
        for (int i = 0; i < 8; i++)
#pragma unroll
            for (int j = 0; j < 8; j++)
                c[i][j] = fmaf(a[i], b[j], c[i][j]);
    }
}

// ---------------------------------------------------------------------------
// 1) l2-normalize both projection batches into g_P
// ---------------------------------------------------------------------------
__global__ void normalize_kernel(const float* __restrict__ p1,
                                 const float* __restrict__ p2, int B) {
    int row = blockIdx.x, l = threadIdx.x;
    const float* src = (row < B) ? (p1 + (size_t)row * D)
                                 : (p2 + (size_t)(row - B) * D);
    float4 v = ((const float4*)src)[l];
    float ss = v.x * v.x + v.y * v.y + v.z * v.z + v.w * v.w;
#pragma unroll
    for (int off = 16; off > 0; off >>= 1)
        ss += __shfl_xor_sync(0xffffffffu, ss, off);
    float inv = 1.0f / sqrtf(ss);
    float4 o = make_float4(v.x * inv, v.y * inv, v.z * inv, v.w * inv);
    ((float4*)g_P)[(size_t)row * 32 + l] = o;
}

// ---------------------------------------------------------------------------
// 2) NN argmax: rows of g_P vs queue, fused GEMM + running argmax
// ---------------------------------------------------------------------------
__global__ __launch_bounds__(256) void nn_kernel(const float* __restrict__ queue,
                                                 int BALL, int rps) {
    extern __shared__ float smem[];
    float* sp = smem;               // p tile   128x128 (swizzled k-major)
    float* sq = smem + 128 * 128;   // q chunk  128x128
    int tid = threadIdx.x, tx = tid & 15, ty = tid >> 4;
    int rowbase = blockIdx.x * 128;

    load_tile_sw(g_P + (size_t)rowbase * D, sp, tid);

    unsigned long long best[8];
#pragma unroll
    for (int i = 0; i < 8; i++) best[i] = 0ull;

    int q0 = blockIdx.y * rps;
    int nch = rps >> 7;
    for (int ch = 0; ch < nch; ch++) {
        __syncthreads();
        load_tile_sw(queue + (size_t)(q0 + ch * 128) * D, sq, tid);
        __syncthreads();

        float c[8][8];
#pragma unroll
        for (int i = 0; i < 8; i++)
#pragma unroll
            for (int j = 0; j < 8; j++) c[i][j] = 0.f;

        mm_tile(sp, sq, tx, ty, c);

        int qb = q0 + ch * 128;
#pragma unroll
        for (int i = 0; i < 8; i++) {
            float bv = c[i][0];
            int bj = 0;
#pragma unroll
            for (int j = 1; j < 8; j++)
                if (c[i][j] > bv) { bv = c[i][j]; bj = j; }
            int col = (bj < 4) ? (4 * tx + bj) : (64 + 4 * tx + bj - 4);
            unsigned gidx = (unsigned)(qb + col);
            // key: larger sim wins; ties -> smaller index (matches jnp.argmax)
            unsigned long long key =
                ((unsigned long long)ford(bv) << 32) |
                (unsigned long long)(0xFFFFFFFFu - gidx);
#pragma unroll
            for (int off = 8; off > 0; off >>= 1) {
                unsigned long long o = __shfl_down_sync(0xffffffffu, key, off, 16);
                if (o > key) key = o;
            }
            if (key > best[i]) best[i] = key;   // only tx==0 lanes meaningful
        }
    }

    if (tx == 0) {
#pragma unroll
        for (int i = 0; i < 8; i++) {
            int row = rowbase + ((i < 4) ? (4 * ty + i) : (64 + 4 * ty + i - 4));
            g_part[(size_t)blockIdx.y * BALL + row] = best[i];
        }
    }
}

// ---------------------------------------------------------------------------
// 3) combine per-split argmax partials -> g_idx
// ---------------------------------------------------------------------------
__global__ void combine_kernel(int BALL) {
    int row = blockIdx.x * blockDim.x + threadIdx.x;
    if (row >= BALL) return;
    unsigned long long best = 0ull;
#pragma unroll
    for (int s = 0; s < QSPLIT; s++) {
        unsigned long long v = g_part[(size_t)s * BALL + row];
        if (v > best) best = v;
    }
    g_idx[row] = (int)(0xFFFFFFFFu - (unsigned)(best & 0xFFFFFFFFull));
}

// ---------------------------------------------------------------------------
// 4) gather nearest neighbours
// ---------------------------------------------------------------------------
__global__ void gather_kernel(const float* __restrict__ queue) {
    int row = blockIdx.x, l = threadIdx.x;
    int idx = g_idx[row];
    ((float4*)g_NN)[(size_t)row * 32 + l] =
        ((const float4*)queue)[(size_t)idx * 32 + l];
}

// ---------------------------------------------------------------------------
// 5) M_z = NN_z @ P_other^T, write /T both direct and transposed into g_logits
//    layout: rows [0,B)=M1, [B,2B)=M1^T, [2B,3B)=M2, [3B,4B)=M2^T
// ---------------------------------------------------------------------------
__global__ __launch_bounds__(256) void gemm_logits_kernel(int B, float invT) {
    extern __shared__ float smem[];
    float* sp = smem;
    float* sq = smem + 128 * 128;
    int tid = threadIdx.x, tx = tid & 15, ty = tid >> 4;
    int z = blockIdx.z;

    const float* A = g_NN + (size_t)(z * B + blockIdx.x * 128) * D;
    const float* Bm = g_P + (size_t)((z ? 0 : B) + blockIdx.y * 128) * D;

    load_tile_sw(A, sp, tid);
    load_tile_sw(Bm, sq, tid);
    __syncthreads();

    float c[8][8];
#pragma unroll
    for (int i = 0; i < 8; i++)
#pragma unroll
        for (int j = 0; j < 8; j++) c[i][j] = 0.f;

    mm_tile(sp, sq, tx, ty, c);

    int rowA0 = blockIdx.x * 128, colB0 = blockIdx.y * 128;
    float* Ld = g_logits + (size_t)(2 * B * z) * B;
    float* Lt = g_logits + (size_t)(2 * B * z + B) * B;

#pragma unroll
    for (int i = 0; i < 8; i++) {
        int rA = rowA0 + ((i < 4) ? (4 * ty + i) : (64 + 4 * ty + i - 4));
        float4 v0 = make_float4(c[i][0] * invT, c[i][1] * invT,
                                c[i][2] * invT, c[i][3] * invT);
        float4 v1 = make_float4(c[i][4] * invT, c[i][5] * invT,
                                c[i][6] * invT, c[i][7] * invT);
        *(float4*)(Ld + (size_t)rA * B + colB0 + 4 * tx) = v0;
        *(float4*)(Ld + (size_t)rA * B + colB0 + 64 + 4 * tx) = v1;
    }
#pragma unroll
    for (int j = 0; j < 8; j++) {
        int cB = colB0 + ((j < 4) ? (4 * tx + j) : (64 + 4 * tx + j - 4));
        float4 t0 = make_float4(c[0][j] * invT, c[1][j] * invT,
                                c[2][j] * invT, c[3][j] * invT);
        float4 t1 = make_float4(c[4][j] * invT, c[5][j] * invT,
                                c[6][j] * invT, c[7][j] * invT);
        *(float4*)(Lt + (size_t)cB * B + rowA0 + 4 * ty) = t0;
        *(float4*)(Lt + (size_t)cB * B + rowA0 + 64 + 4 * ty) = t1;
    }
}

// ---------------------------------------------------------------------------
// 6) per-row log-softmax loss
// ---------------------------------------------------------------------------
__global__ void lse_loss_kernel(float* __restrict__ out, int B) {
    int row = blockIdx.x;
    const float* r = g_logits + (size_t)row * B;
    float m = -1e30f, s = 0.f;
    for (int t = threadIdx.x; t < B; t += blockDim.x) {
        float v = r[t];
        if (v > m) { s = s * __expf(m - v) + 1.f; m = v; }
        else       { s += __expf(v - m); }
    }
    unsigned lane = threadIdx.x & 31, w = threadIdx.x >> 5;
#pragma unroll
    for (int off = 16; off > 0; off >>= 1) {
        float om = __shfl_down_sync(0xffffffffu, m, off);
        float os = __shfl_down_sync(0xffffffffu, s, off);
        float nm = fmaxf(m, om);
        s = s * __expf(m - nm) + os * __expf(om - nm);
        m = nm;
    }
    __shared__ float shm[8], shs[8];
    if (lane == 0) { shm[w] = m; shs[w] = s; }
    __syncthreads();
    if (threadIdx.x == 0) {
        m = shm[0]; s = shs[0];
#pragma unroll
        for (int k = 1; k < 8; k++) {
            float nm = fmaxf(m, shm[k]);
            s = s * __expf(m - nm) + shs[k] * __expf(shm[k] - nm);
            m = nm;
        }
        out[row] = (m + logf(s)) - r[row % B];
    }
}

// ---------------------------------------------------------------------------
extern "C" void kernel_launch(void* const* d_in, const int* in_sizes, int n_in,
                              void* d_out, int out_size) {
    const float* p1 = (const float*)d_in[0];
    const float* p2 = (const float*)d_in[1];
    const float* queue = (const float*)d_in[2];
    int B = in_sizes[0] / D;     // 2048
    int Q = in_sizes[2] / D;     // 65536
    int BALL = 2 * B;
    float* out = (float*)d_out;

    cudaFuncSetAttribute(nn_kernel,
                         cudaFuncAttributeMaxDynamicSharedMemorySize, 131072);
    cudaFuncSetAttribute(gemm_logits_kernel,
                         cudaFuncAttributeMaxDynamicSharedMemorySize, 131072);

    normalize_kernel<<<BALL, 32>>>(p1, p2, B);

    int rps = Q / QSPLIT;
    nn_kernel<<<dim3(BALL / 128, QSPLIT), 256, 131072>>>(queue, BALL, rps);

    combine_kernel<<<(BALL + 255) / 256, 256>>>(BALL);
    gather_kernel<<<BALL, 32>>>(queue);

    gemm_logits_kernel<<<dim3(B / 128, B / 128, 2), 256, 131072>>>(B, 10.0f);

    lse_loss_kernel<<<4 * B, 256>>>(out, B);
}

// round 3
// speedup vs baseline: 1.5636x; 1.5636x over previous
#include <cuda_runtime.h>
#include <cuda_bf16.h>
#include <math.h>

#define D 128
#define NSPLIT 4
#define THR 4e-5f
#define MAXFLAG 128

// ---- static scratch ----
__device__ float g_P[4096 * 128];
__device__ __nv_bfloat16 g_Ah[4096 * 128];
__device__ __nv_bfloat16 g_Al[4096 * 128];
__device__ __nv_bfloat16 g_Qh[65536 * 128];
__device__ __nv_bfloat16 g_Ql[65536 * 128];
__device__ float g_NN[4096 * 128];
__device__ float g_t1v[NSPLIT * 4096];
__device__ float g_t2v[NSPLIT * 4096];
__device__ int   g_t1c[NSPLIT * 4096];
__device__ int   g_idx[4096];
__device__ int   g_nflag;
__device__ int   g_flaglist[MAXFLAG];
__device__ unsigned long long g_fbkey[MAXFLAG];
__device__ float g_logits[8192 * 2048];

// swizzled bf16 tile addressing: 128 rows x 128 cols, 256B/row, 16B chunks
#define TSW(r, c) (((r) * 256) + ((((c) ^ ((r) & 7))) << 4))

__device__ __forceinline__ unsigned smem_u32(const void* p) {
    unsigned a;
    asm("{ .reg .u64 t; cvta.to.shared.u64 t, %1; cvt.u32.u64 %0, t; }"
        : "=r"(a) : "l"(p));
    return a;
}
__device__ __forceinline__ void cp_async16(unsigned sm, const void* g) {
    asm volatile("cp.async.cg.shared.global [%0], [%1], 16;"
                 :: "r"(sm), "l"(g));
}
__device__ __forceinline__ void cp_commit() {
    asm volatile("cp.async.commit_group;");
}
__device__ __forceinline__ void ldsm4(unsigned& r0, unsigned& r1, unsigned& r2,
                                      unsigned& r3, unsigned addr) {
    asm volatile("ldmatrix.sync.aligned.m8n8.x4.shared.b16 {%0,%1,%2,%3}, [%4];"
                 : "=r"(r0), "=r"(r1), "=r"(r2), "=r"(r3) : "r"(addr));
}
__device__ __forceinline__ void mma16816(float c[4], const unsigned a[4],
                                         unsigned b0, unsigned b1) {
    asm volatile("mma.sync.aligned.m16n8k16.row.col.f32.bf16.bf16.f32 "
                 "{%0,%1,%2,%3}, {%4,%5,%6,%7}, {%8,%9}, {%0,%1,%2,%3};"
                 : "+f"(c[0]), "+f"(c[1]), "+f"(c[2]), "+f"(c[3])
                 : "r"(a[0]), "r"(a[1]), "r"(a[2]), "r"(a[3]), "r"(b0), "r"(b1));
}
__device__ __forceinline__ unsigned ford(float f) {
    unsigned u = __float_as_uint(f);
    return (u & 0x80000000u) ? ~u : (u | 0x80000000u);
}

// ---------------------------------------------------------------------------
// 1) normalize -> g_P fp32 + g_Ah/g_Al bf16 split; also zero g_nflag
// ---------------------------------------------------------------------------
__global__ void normalize_kernel(const float* __restrict__ p1,
                                 const float* __restrict__ p2, int B) {
    if (blockIdx.x == 0 && threadIdx.x == 0) g_nflag = 0;
    int row = blockIdx.x, l = threadIdx.x;
    const float* src = (row < B) ? (p1 + (size_t)row * D)
                                 : (p2 + (size_t)(row - B) * D);
    float4 v = ((const float4*)src)[l];
    float ss = v.x * v.x + v.y * v.y + v.z * v.z + v.w * v.w;
#pragma unroll
    for (int off = 16; off > 0; off >>= 1)
        ss += __shfl_xor_sync(0xffffffffu, ss, off);
    float inv = 1.0f / sqrtf(ss);
    float4 o = make_float4(v.x * inv, v.y * inv, v.z * inv, v.w * inv);
    ((float4*)g_P)[(size_t)row * 32 + l] = o;
    float f[4] = {o.x, o.y, o.z, o.w};
    __nv_bfloat16 hi[4], lo[4];
#pragma unroll
    for (int i = 0; i < 4; i++) {
        hi[i] = __float2bfloat16(f[i]);
        lo[i] = __float2bfloat16(f[i] - __bfloat162float(hi[i]));
    }
    *(uint2*)(g_Ah + (size_t)row * D + 4 * l) = *(uint2*)hi;
    *(uint2*)(g_Al + (size_t)row * D + 4 * l) = *(uint2*)lo;
}

// ---------------------------------------------------------------------------
// 2) split queue -> bf16 hi/lo
// ---------------------------------------------------------------------------
__global__ void convq_kernel(const float* __restrict__ queue) {
    int i = blockIdx.x * blockDim.x + threadIdx.x;   // one float4 per thread
    float4 v = ((const float4*)queue)[i];
    float f[4] = {v.x, v.y, v.z, v.w};
    __nv_bfloat16 hi[4], lo[4];
#pragma unroll
    for (int k = 0; k < 4; k++) {
        hi[k] = __float2bfloat16(f[k]);
        lo[k] = __float2bfloat16(f[k] - __bfloat162float(hi[k]));
    }
    *(uint2*)(g_Qh + 4 * (size_t)i) = *(uint2*)hi;
    *(uint2*)(g_Ql + 4 * (size_t)i) = *(uint2*)lo;
}

// ---------------------------------------------------------------------------
// 3) NN search: split-bf16 HMMA, per-row top-2 tracking
//    grid (32 row-blocks, NSPLIT), 256 threads, 192KB smem
// ---------------------------------------------------------------------------
#define OFF_AH 0
#define OFF_AL 32768
#define OFF_B  65536        // 2 buffers x (hi 32KB + lo 32KB)
#define SMEM_NN 196608

__global__ __launch_bounds__(256, 1)
void nn_kernel(int rps) {
    extern __shared__ char smem[];
    unsigned sb = smem_u32(smem);
    int tid = threadIdx.x, lane = tid & 31, wid = tid >> 5;
    int wm = wid >> 2, wn = wid & 3;
    int rowbase = blockIdx.x * 128;
    int q0 = blockIdx.y * rps;
    int nch = rps >> 7;

    // load A (hi/lo) into swizzled smem
    {
        int r = tid >> 1, h = tid & 1;
        const uint4* sh = (const uint4*)(g_Ah + (size_t)(rowbase + r) * D);
        const uint4* sl = (const uint4*)(g_Al + (size_t)(rowbase + r) * D);
#pragma unroll
        for (int i = 0; i < 8; i++) {
            int c = 8 * h + i;
            unsigned o = TSW(r, c);
            *(uint4*)(smem + OFF_AH + o) = sh[c];
            *(uint4*)(smem + OFF_AL + o) = sl[c];
        }
    }

    // B chunk loader via cp.async
    int brow = tid >> 1, bh = tid & 1;
    auto issueB = [&](int ch) {
        unsigned bdst = sb + OFF_B + (unsigned)(ch & 1) * 65536u;
        const __nv_bfloat16* qh = g_Qh + (size_t)(q0 + ch * 128 + brow) * D;
        const __nv_bfloat16* ql = g_Ql + (size_t)(q0 + ch * 128 + brow) * D;
#pragma unroll
        for (int i = 0; i < 8; i++) {
            int c = 8 * bh + i;
            unsigned o = TSW(brow, c);
            cp_async16(bdst + o, qh + c * 8);
            cp_async16(bdst + 32768u + o, ql + c * 8);
        }
        cp_commit();
    };
    issueB(0);

    float best1[8], best2[8];
    int bcol[8];
#pragma unroll
    for (int s = 0; s < 8; s++) { best1[s] = -INFINITY; best2[s] = -INFINITY; bcol[s] = 0; }

    // ldmatrix lane addressing pieces
    int a_r = ((lane >> 3) & 1) * 8 + (lane & 7);   // + rbase
    int a_cq = lane >> 4;                           // + c0
    int b_r = ((lane >> 4) << 3) + (lane & 7);      // + nbase
    int b_cq = (lane >> 3) & 1;                     // + c0

    for (int ch = 0; ch < nch; ch++) {
        if (ch + 1 < nch) {
            issueB(ch + 1);
            asm volatile("cp.async.wait_group 1;");
        } else {
            asm volatile("cp.async.wait_group 0;");
        }
        __syncthreads();

        unsigned bhb = sb + OFF_B + (unsigned)(ch & 1) * 65536u;
        unsigned blb = bhb + 32768u;

        float acc[4][4][4];
#pragma unroll
        for (int mt = 0; mt < 4; mt++)
#pragma unroll
            for (int nt = 0; nt < 4; nt++)
#pragma unroll
                for (int e = 0; e < 4; e++) acc[mt][nt][e] = 0.f;

#pragma unroll
        for (int ks = 0; ks < 8; ks++) {
            int c0 = 2 * ks;
            unsigned bhf[8], blf[8];
#pragma unroll
            for (int nt2 = 0; nt2 < 2; nt2++) {
                int n = wn * 32 + nt2 * 16 + b_r;
                unsigned o = TSW(n, c0 + b_cq);
                ldsm4(bhf[4 * nt2], bhf[4 * nt2 + 1], bhf[4 * nt2 + 2],
                      bhf[4 * nt2 + 3], bhb + o);
                ldsm4(blf[4 * nt2], blf[4 * nt2 + 1], blf[4 * nt2 + 2],
                      blf[4 * nt2 + 3], blb + o);
            }
            unsigned ahf[4][4], alf[4][4];
#pragma unroll
            for (int mt = 0; mt < 4; mt++) {
                int r = wm * 64 + mt * 16 + a_r;
                unsigned o = TSW(r, c0 + a_cq);
                ldsm4(ahf[mt][0], ahf[mt][1], ahf[mt][2], ahf[mt][3],
                      sb + OFF_AH + o);
                ldsm4(alf[mt][0], alf[mt][1], alf[mt][2], alf[mt][3],
                      sb + OFF_AL + o);
            }
#pragma unroll
            for (int mt = 0; mt < 4; mt++)
#pragma unroll
                for (int nt = 0; nt < 4; nt++) {
                    unsigned b0 = bhf[(nt >> 1) * 4 + (nt & 1) * 2];
                    unsigned b1 = bhf[(nt >> 1) * 4 + (nt & 1) * 2 + 1];
                    unsigned l0 = blf[(nt >> 1) * 4 + (nt & 1) * 2];
                    unsigned l1 = blf[(nt >> 1) * 4 + (nt & 1) * 2 + 1];
                    mma16816(acc[mt][nt], ahf[mt], b0, b1);
                    mma16816(acc[mt][nt], alf[mt], b0, b1);
                    mma16816(acc[mt][nt], ahf[mt], l0, l1);
                }
        }
        __syncthreads();   // done with buf before loader overwrites (next-next)

        // top-2 scan (cols ascending within a slot)
        int qb = q0 + ch * 128 + wn * 32 + 2 * (lane & 3);
#pragma unroll
        for (int mt = 0; mt < 4; mt++)
#pragma unroll
            for (int p = 0; p < 2; p++) {
                int s = mt * 2 + p;
#pragma unroll
                for (int nt = 0; nt < 4; nt++)
#pragma unroll
                    for (int e = 0; e < 2; e++) {
                        float v = acc[mt][nt][p * 2 + e];
                        int col = qb + nt * 8 + e;
                        if (v > best1[s]) {
                            best2[s] = best1[s]; best1[s] = v; bcol[s] = col;
                        } else if (v > best2[s]) best2[s] = v;
                    }
            }
    }

    // reduce across 4 lanes of the quad (same rows, different cols)
    float* sred1 = (float*)(smem + OFF_B);
    float* sred2 = (float*)(smem + OFF_B + 2048);
    int*   sredc = (int*)(smem + OFF_B + 4096);
#pragma unroll
    for (int s = 0; s < 8; s++) {
        float b1 = best1[s], b2 = best2[s];
        int c1 = bcol[s];
#pragma unroll
        for (int off = 1; off <= 2; off <<= 1) {
            float ob1 = __shfl_xor_sync(0xffffffffu, b1, off);
            float ob2 = __shfl_xor_sync(0xffffffffu, b2, off);
            int   oc1 = __shfl_xor_sync(0xffffffffu, c1, off);
            if (ob1 > b1 || (ob1 == b1 && oc1 < c1)) {
                b2 = fmaxf(b1, ob2); b1 = ob1; c1 = oc1;
            } else {
                b2 = fmaxf(b2, ob1);
            }
        }
        if ((lane & 3) == 0) {
            int row = wm * 64 + (s >> 1) * 16 + (s & 1) * 8 + (lane >> 2);
            sred1[wn * 128 + row] = b1;
            sred2[wn * 128 + row] = b2;
            sredc[wn * 128 + row] = c1;
        }
    }
    __syncthreads();
    if (tid < 128) {
        float b1 = sred1[tid], b2 = sred2[tid];
        int c1 = sredc[tid];
#pragma unroll
        for (int w = 1; w < 4; w++) {
            float ob1 = sred1[w * 128 + tid], ob2 = sred2[w * 128 + tid];
            int oc1 = sredc[w * 128 + tid];
            if (ob1 > b1 || (ob1 == b1 && oc1 < c1)) {
                b2 = fmaxf(b1, ob2); b1 = ob1; c1 = oc1;
            } else {
                b2 = fmaxf(b2, ob1);
            }
        }
        size_t o = (size_t)blockIdx.y * 4096 + rowbase + tid;
        g_t1v[o] = b1; g_t2v[o] = b2; g_t1c[o] = c1;
    }
}

// ---------------------------------------------------------------------------
// 4) combine splits, flag uncertain rows
// ---------------------------------------------------------------------------
__global__ void combine_kernel(int BALL) {
    int row = blockIdx.x * blockDim.x + threadIdx.x;
    if (row >= BALL) return;
    float b1 = g_t1v[row], b2 = g_t2v[row];
    int c1 = g_t1c[row];
#pragma unroll
    for (int s = 1; s < NSPLIT; s++) {
        float ob1 = g_t1v[(size_t)s * 4096 + row];
        float ob2 = g_t2v[(size_t)s * 4096 + row];
        int oc1 = g_t1c[(size_t)s * 4096 + row];
        if (ob1 > b1 || (ob1 == b1 && oc1 < c1)) {
            b2 = fmaxf(b1, ob2); b1 = ob1; c1 = oc1;
        } else {
            b2 = fmaxf(b2, ob1);
        }
    }
    g_idx[row] = c1;
    if (b1 - b2 < THR) {
        int slot = atomicAdd(&g_nflag, 1);
        if (slot < MAXFLAG) {
            g_flaglist[slot] = row;
            g_fbkey[slot] = 0ull;
        }
    }
}

// ---------------------------------------------------------------------------
// 5) exact fp32 fallback for flagged rows (one shared queue pass)
//    grid 256 CTAs x 256 thr; thread owns one queue row
// ---------------------------------------------------------------------------
__global__ __launch_bounds__(256, 1)
void fallback_kernel(const float* __restrict__ queue) {
    int nf = g_nflag;
    if (nf == 0) return;
    if (nf > MAXFLAG) nf = MAXFLAG;

    extern __shared__ float fsm[];                  // [nf][128] P rows
    __shared__ unsigned long long skey[MAXFLAG];
    for (int i = threadIdx.x; i < nf * 128; i += 256)
        fsm[i] = g_P[(size_t)g_flaglist[i >> 7] * D + (i & 127)];
    for (int i = threadIdx.x; i < nf; i += 256) skey[i] = 0ull;
    __syncthreads();

    int q = blockIdx.x * 256 + threadIdx.x;         // 65536 threads total
    float4 qr[32];
    const float4* qp = (const float4*)(queue + (size_t)q * D);
#pragma unroll
    for (int i = 0; i < 32; i++) qr[i] = qp[i];

    for (int f = 0; f < nf; f++) {
        const float4* pr = (const float4*)(fsm + f * 128);
        float s0 = 0.f, s1 = 0.f, s2 = 0.f, s3 = 0.f;
#pragma unroll
        for (int i = 0; i < 32; i++) {
            float4 p = pr[i];
            s0 = fmaf(qr[i].x, p.x, s0);
            s1 = fmaf(qr[i].y, p.y, s1);
            s2 = fmaf(qr[i].z, p.z, s2);
            s3 = fmaf(qr[i].w, p.w, s3);
        }
        float dot = (s0 + s1) + (s2 + s3);
        unsigned long long key =
            ((unsigned long long)ford(dot) << 32) |
            (unsigned long long)(0xFFFFFFFFu - (unsigned)q);
#pragma unroll
        for (int off = 16; off > 0; off >>= 1) {
            unsigned long long o = __shfl_xor_sync(0xffffffffu, key, off);
            if (o > key) key = o;
        }
        if ((threadIdx.x & 31) == 0) atomicMax(&skey[f], key);
    }
    __syncthreads();
    for (int f = threadIdx.x; f < nf; f += 256)
        atomicMax(&g_fbkey[f], skey[f]);
}

__global__ void fixup_kernel() {
    int nf = g_nflag;
    if (nf > MAXFLAG) nf = MAXFLAG;
    int s = threadIdx.x;
    if (s < nf)
        g_idx[g_flaglist[s]] =
            (int)(0xFFFFFFFFu - (unsigned)(g_fbkey[s] & 0xFFFFFFFFull));
}

// ---------------------------------------------------------------------------
// 6) gather NN rows
// ---------------------------------------------------------------------------
__global__ void gather_kernel(const float* __restrict__ queue) {
    int row = blockIdx.x, l = threadIdx.x;
    int idx = g_idx[row];
    ((float4*)g_NN)[(size_t)row * 32 + l] =
        ((const float4*)queue)[(size_t)idx * 32 + l];
}

// ---------------------------------------------------------------------------
// fp32 register-tile GEMM for logits (round-1 proven)
// ---------------------------------------------------------------------------
__device__ __forceinline__ void load_tile_sw(const float* __restrict__ src,
                                             float* sm, int tid) {
    int w = tid >> 5, l = tid & 31;
#pragma unroll
    for (int m = 0; m < 16; m++) {
        int r = w + m * 8;
        float4 v = *(const float4*)(src + (size_t)r * D + 4 * l);
        int slot = (((r >> 2) ^ l) << 2) + (r & 3);
        sm[(4 * l + 0) * 128 + slot] = v.x;
        sm[(4 * l + 1) * 128 + slot] = v.y;
        sm[(4 * l + 2) * 128 + slot] = v.z;
        sm[(4 * l + 3) * 128 + slot] = v.w;
    }
}

__device__ __forceinline__ void mm_tile(const float* sp, const float* sq,
                                        int tx, int ty, float c[8][8]) {
    const float4* sp4 = (const float4*)sp;
    const float4* sq4 = (const float4*)sq;
#pragma unroll 4
    for (int k = 0; k < 128; k++) {
        int s = (k >> 2) & 31;
        float4 A0 = sp4[k * 32 + (ty ^ s)];
        float4 A1 = sp4[k * 32 + ((ty + 16) ^ s)];
        float4 B0 = sq4[k * 32 + (tx ^ s)];
        float4 B1 = sq4[k * 32 + ((tx + 16) ^ s)];
        float a[8] = {A0.x, A0.y, A0.z, A0.w, A1.x, A1.y, A1.z, A1.w};
        float b[8] = {B0.x, B0.y, B0.z, B0.w, B1.x, B1.y, B1.z, B1.w};
#pragma unroll
        for (int i = 0; i < 8; i++)
#pragma unroll
            for (int j = 0; j < 8; j++)
                c[i][j] = fmaf(a[i], b[j], c[i][j]);
    }
}

__global__ __launch_bounds__(256) void gemm_logits_kernel(int B, float invT) {
    extern __shared__ float smemf[];
    float* sp = smemf;
    float* sq = smemf + 128 * 128;
    int tid = threadIdx.x, tx = tid & 15, ty = tid >> 4;
    int z = blockIdx.z;

    const float* A = g_NN + (size_t)(z * B + blockIdx.x * 128) * D;
    const float* Bm = g_P + (size_t)((z ? 0 : B) + blockIdx.y * 128) * D;

    load_tile_sw(A, sp, tid);
    load_tile_sw(Bm, sq, tid);
    __syncthreads();

    float c[8][8];
#pragma unroll
    for (int i = 0; i < 8; i++)
#pragma unroll
        for (int j = 0; j < 8; j++) c[i][j] = 0.f;

    mm_tile(sp, sq, tx, ty, c);

    int rowA0 = blockIdx.x * 128, colB0 = blockIdx.y * 128;
    float* Ld = g_logits + (size_t)(2 * B * z) * B;
    float* Lt = g_logits + (size_t)(2 * B * z + B) * B;

#pragma unroll
    for (int i = 0; i < 8; i++) {
        int rA = rowA0 + ((i < 4) ? (4 * ty + i) : (64 + 4 * ty + i - 4));
        float4 v0 = make_float4(c[i][0] * invT, c[i][1] * invT,
                                c[i][2] * invT, c[i][3] * invT);
        float4 v1 = make_float4(c[i][4] * invT, c[i][5] * invT,
                                c[i][6] * invT, c[i][7] * invT);
        *(float4*)(Ld + (size_t)rA * B + colB0 + 4 * tx) = v0;
        *(float4*)(Ld + (size_t)rA * B + colB0 + 64 + 4 * tx) = v1;
    }
#pragma unroll
    for (int j = 0; j < 8; j++) {
        int cB = colB0 + ((j < 4) ? (4 * tx + j) : (64 + 4 * tx + j - 4));
        float4 t0 = make_float4(c[0][j] * invT, c[1][j] * invT,
                                c[2][j] * invT, c[3][j] * invT);
        float4 t1 = make_float4(c[4][j] * invT, c[5][j] * invT,
                                c[6][j] * invT, c[7][j] * invT);
        *(float4*)(Lt + (size_t)cB * B + rowA0 + 4 * ty) = t0;
        *(float4*)(Lt + (size_t)cB * B + rowA0 + 64 + 4 * ty) = t1;
    }
}

// ---------------------------------------------------------------------------
// 7) per-row log-softmax loss
// ---------------------------------------------------------------------------
__global__ void lse_loss_kernel(float* __restrict__ out, int B) {
    int row = blockIdx.x;
    const float* r = g_logits + (size_t)row * B;
    float m = -1e30f, s = 0.f;
    for (int t = threadIdx.x; t < B; t += blockDim.x) {
        float v = r[t];
        if (v > m) { s = s * __expf(m - v) + 1.f; m = v; }
        else       { s += __expf(v - m); }
    }
    unsigned lane = threadIdx.x & 31, w = threadIdx.x >> 5;
#pragma unroll
    for (int off = 16; off > 0; off >>= 1) {
        float om = __shfl_down_sync(0xffffffffu, m, off);
        float os = __shfl_down_sync(0xffffffffu, s, off);
        float nm = fmaxf(m, om);
        s = s * __expf(m - nm) + os * __expf(om - nm);
        m = nm;
    }
    __shared__ float shm[8], shs[8];
    if (lane == 0) { shm[w] = m; shs[w] = s; }
    __syncthreads();
    if (threadIdx.x == 0) {
        m = shm[0]; s = shs[0];
#pragma unroll
        for (int k = 1; k < 8; k++) {
            float nm = fmaxf(m, shm[k]);
            s = s * __expf(m - nm) + shs[k] * __expf(shm[k] - nm);
            m = nm;
        }
        out[row] = (m + logf(s)) - r[row % B];
    }
}

// ---------------------------------------------------------------------------
extern "C" void kernel_launch(void* const* d_in, const int* in_sizes, int n_in,
                              void* d_out, int out_size) {
    const float* p1 = (const float*)d_in[0];
    const float* p2 = (const float*)d_in[1];
    const float* queue = (const float*)d_in[2];
    int B = in_sizes[0] / D;     // 2048
    int Q = in_sizes[2] / D;     // 65536
    int BALL = 2 * B;
    float* out = (float*)d_out;

    cudaFuncSetAttribute(nn_kernel,
                         cudaFuncAttributeMaxDynamicSharedMemorySize, SMEM_NN);
    cudaFuncSetAttribute(fallback_kernel,
                         cudaFuncAttributeMaxDynamicSharedMemorySize, 65536);
    cudaFuncSetAttribute(gemm_logits_kernel,
                         cudaFuncAttributeMaxDynamicSharedMemorySize, 131072);

    normalize_kernel<<<BALL, 32>>>(p1, p2, B);
    convq_kernel<<<(Q * D / 4) / 256, 256>>>(queue);

    int rps = Q / NSPLIT;
    nn_kernel<<<dim3(BALL / 128, NSPLIT), 256, SMEM_NN>>>(rps);

    combine_kernel<<<(BALL + 255) / 256, 256>>>(BALL);
    fallback_kernel<<<Q / 256, 256, 65536>>>(queue);
    fixup_kernel<<<1, MAXFLAG>>>();
    gather_kernel<<<BALL, 32>>>(queue);

    gemm_logits_kernel<<<dim3(B / 128, B / 128, 2), 256, 131072>>>(B, 10.0f);

    lse_loss_kernel<<<4 * B, 256>>>(out, B);
}

// round 4
// speedup vs baseline: 2.7119x; 1.7344x over previous
#include <cuda_runtime.h>
#include <cuda_bf16.h>
#include <math.h>

#define D 128
#define NSPLIT 4
#define CAP 128
#define MAXFLAG 128
#define T0 0.30f
#define DELTA 0.0165f

// ---- static scratch ----
__device__ float g_P[4096 * 128];
__device__ __nv_bfloat16 g_Ah[4096 * 128];
__device__ __nv_bfloat16 g_Qh[65536 * 128];
__device__ float g_NN[4096 * 128];
__device__ int      g_cand[4096 * CAP];
__device__ int      g_cnt[4096];
__device__ unsigned g_bestu[4096];
__device__ int   g_idx[4096];
__device__ int   g_nflag;
__device__ int   g_flaglist[MAXFLAG];
__device__ unsigned long long g_fbkey[MAXFLAG];
__device__ float g_logits[8192 * 2048];

// swizzled bf16 tile addressing: 128 rows x 128 cols, 256B/row, 16B chunks
#define TSW(r, c) (((r) * 256) + ((((c) ^ ((r) & 7))) << 4))

__device__ __forceinline__ unsigned smem_u32(const void* p) {
    unsigned a;
    asm("{ .reg .u64 t; cvta.to.shared.u64 t, %1; cvt.u32.u64 %0, t; }"
        : "=r"(a) : "l"(p));
    return a;
}
__device__ __forceinline__ void cp_async16(unsigned sm, const void* g) {
    asm volatile("cp.async.cg.shared.global [%0], [%1], 16;" :: "r"(sm), "l"(g));
}
__device__ __forceinline__ void cp_commit() {
    asm volatile("cp.async.commit_group;");
}
__device__ __forceinline__ void ldsm4(unsigned& r0, unsigned& r1, unsigned& r2,
                                      unsigned& r3, unsigned addr) {
    asm volatile("ldmatrix.sync.aligned.m8n8.x4.shared.b16 {%0,%1,%2,%3}, [%4];"
                 : "=r"(r0), "=r"(r1), "=r"(r2), "=r"(r3) : "r"(addr));
}
__device__ __forceinline__ void mma16816(float c[4], const unsigned a[4],
                                         unsigned b0, unsigned b1) {
    asm volatile("mma.sync.aligned.m16n8k16.row.col.f32.bf16.bf16.f32 "
                 "{%0,%1,%2,%3}, {%4,%5,%6,%7}, {%8,%9}, {%0,%1,%2,%3};"
                 : "+f"(c[0]), "+f"(c[1]), "+f"(c[2]), "+f"(c[3])
                 : "r"(a[0]), "r"(a[1]), "r"(a[2]), "r"(a[3]), "r"(b0), "r"(b1));
}
__device__ __forceinline__ unsigned ford(float f) {
    unsigned u = __float_as_uint(f);
    return (u & 0x80000000u) ? ~u : (u | 0x80000000u);
}
__device__ __forceinline__ float unford(unsigned k) {
    unsigned u = (k & 0x80000000u) ? (k ^ 0x80000000u) : ~k;
    return __uint_as_float(u);
}

// ---------------------------------------------------------------------------
// 0) re-init per-call state (graph-replay determinism)
// ---------------------------------------------------------------------------
__global__ void init_kernel() {
    int i = blockIdx.x * blockDim.x + threadIdx.x;
    if (i < 4096) { g_cnt[i] = 0; g_bestu[i] = 0u; }
    if (i == 0) g_nflag = 0;
}

// ---------------------------------------------------------------------------
// 1) normalize -> g_P fp32 + g_Ah bf16(hi)
// ---------------------------------------------------------------------------
__global__ void normalize_kernel(const float* __restrict__ p1,
                                 const float* __restrict__ p2, int B) {
    int row = blockIdx.x, l = threadIdx.x;
    const float* src = (row < B) ? (p1 + (size_t)row * D)
                                 : (p2 + (size_t)(row - B) * D);
    float4 v = ((const float4*)src)[l];
    float ss = v.x * v.x + v.y * v.y + v.z * v.z + v.w * v.w;
#pragma unroll
    for (int off = 16; off > 0; off >>= 1)
        ss += __shfl_xor_sync(0xffffffffu, ss, off);
    float inv = 1.0f / sqrtf(ss);
    float4 o = make_float4(v.x * inv, v.y * inv, v.z * inv, v.w * inv);
    ((float4*)g_P)[(size_t)row * 32 + l] = o;
    __nv_bfloat16 hi[4] = {__float2bfloat16(o.x), __float2bfloat16(o.y),
                           __float2bfloat16(o.z), __float2bfloat16(o.w)};
    *(uint2*)(g_Ah + (size_t)row * D + 4 * l) = *(uint2*)hi;
}

// ---------------------------------------------------------------------------
// 2) queue -> bf16 hi
// ---------------------------------------------------------------------------
__global__ void convq_kernel(const float* __restrict__ queue) {
    int i = blockIdx.x * blockDim.x + threadIdx.x;
    float4 v = ((const float4*)queue)[i];
    __nv_bfloat16 hi[4] = {__float2bfloat16(v.x), __float2bfloat16(v.y),
                           __float2bfloat16(v.z), __float2bfloat16(v.w)};
    *(uint2*)(g_Qh + 4 * (size_t)i) = *(uint2*)hi;
}

// ---------------------------------------------------------------------------
// 3) NN screen: 1-term bf16 HMMA + candidate collection
// ---------------------------------------------------------------------------
#define OFF_AH 0
#define OFF_B  32768                     // 2 buffers x 32KB
#define SMEM_NN (32768 + 2 * 32768)

__global__ __launch_bounds__(256, 1)
void nn_kernel(int rps) {
    extern __shared__ char smem[];
    unsigned sb = smem_u32(smem);
    int tid = threadIdx.x, lane = tid & 31, wid = tid >> 5;
    int wm = wid >> 2, wn = wid & 3;
    int rowbase = blockIdx.x * 128;
    int q0 = blockIdx.y * rps;
    int nch = rps >> 7;

    // A (hi) -> swizzled smem
    {
        int r = tid >> 1, h = tid & 1;
        const uint4* sh = (const uint4*)(g_Ah + (size_t)(rowbase + r) * D);
#pragma unroll
        for (int i = 0; i < 8; i++) {
            int c = 8 * h + i;
            *(uint4*)(smem + OFF_AH + TSW(r, c)) = sh[c];
        }
    }

    int brow = tid >> 1, bh = tid & 1;
    auto issueB = [&](int ch) {
        unsigned bdst = sb + OFF_B + (unsigned)(ch & 1) * 32768u;
        const __nv_bfloat16* qh = g_Qh + (size_t)(q0 + ch * 128 + brow) * D;
#pragma unroll
        for (int i = 0; i < 8; i++) {
            int c = 8 * bh + i;
            cp_async16(bdst + TSW(brow, c), qh + c * 8);
        }
        cp_commit();
    };
    issueB(0);

    float best[8];
#pragma unroll
    for (int s = 0; s < 8; s++) best[s] = -INFINITY;

    int a_r = ((lane >> 3) & 1) * 8 + (lane & 7);
    int a_cq = lane >> 4;
    int b_r = ((lane >> 4) << 3) + (lane & 7);
    int b_cq = (lane >> 3) & 1;

    for (int ch = 0; ch < nch; ch++) {
        if (ch + 1 < nch) {
            issueB(ch + 1);
            asm volatile("cp.async.wait_group 1;");
        } else {
            asm volatile("cp.async.wait_group 0;");
        }
        __syncthreads();

        unsigned bhb = sb + OFF_B + (unsigned)(ch & 1) * 32768u;

        float acc[4][4][4];
#pragma unroll
        for (int mt = 0; mt < 4; mt++)
#pragma unroll
            for (int nt = 0; nt < 4; nt++)
#pragma unroll
                for (int e = 0; e < 4; e++) acc[mt][nt][e] = 0.f;

#pragma unroll
        for (int ks = 0; ks < 8; ks++) {
            int c0 = 2 * ks;
            unsigned bf[8];
#pragma unroll
            for (int nt2 = 0; nt2 < 2; nt2++) {
                int n = wn * 32 + nt2 * 16 + b_r;
                ldsm4(bf[4 * nt2], bf[4 * nt2 + 1], bf[4 * nt2 + 2],
                      bf[4 * nt2 + 3], bhb + TSW(n, c0 + b_cq));
            }
            unsigned af[4][4];
#pragma unroll
            for (int mt = 0; mt < 4; mt++) {
                int r = wm * 64 + mt * 16 + a_r;
                ldsm4(af[mt][0], af[mt][1], af[mt][2], af[mt][3],
                      sb + OFF_AH + TSW(r, c0 + a_cq));
            }
#pragma unroll
            for (int mt = 0; mt < 4; mt++)
#pragma unroll
                for (int nt = 0; nt < 4; nt++)
                    mma16816(acc[mt][nt], af[mt],
                             bf[(nt >> 1) * 4 + (nt & 1) * 2],
                             bf[(nt >> 1) * 4 + (nt & 1) * 2 + 1]);
        }
        __syncthreads();

        // epilogue: best tracking + provable candidate collection
        int qb = q0 + ch * 128 + wn * 32 + 2 * (lane & 3);
#pragma unroll
        for (int mt = 0; mt < 4; mt++)
#pragma unroll
            for (int p = 0; p < 2; p++) {
                int s = mt * 2 + p;
                int row = rowbase + wm * 64 + mt * 16 + p * 8 + (lane >> 2);
                float thr = fmaxf(best[s], T0) - DELTA;
#pragma unroll
                for (int nt = 0; nt < 4; nt++)
#pragma unroll
                    for (int e = 0; e < 2; e++) {
                        float v = acc[mt][nt][p * 2 + e];
                        if (v > best[s]) best[s] = v;
                        if (v > thr) {
                            int col = qb + nt * 8 + e;
                            int slot = atomicAdd(&g_cnt[row], 1);
                            if (slot < CAP) g_cand[row * CAP + slot] = col;
                        }
                    }
            }
    }

    // per-row approx max -> g_bestu (for the T0 safety check)
#pragma unroll
    for (int s = 0; s < 8; s++) {
        float b = best[s];
#pragma unroll
        for (int off = 1; off <= 2; off <<= 1)
            b = fmaxf(b, __shfl_xor_sync(0xffffffffu, b, off));
        if ((lane & 3) == 0) {
            int row = rowbase + wm * 64 + (s >> 1) * 16 + (s & 1) * 8 + (lane >> 2);
            atomicMax(&g_bestu[row], ford(b));
        }
    }
}

// ---------------------------------------------------------------------------
// 4) verify: flag rows where the collection guarantee doesn't hold
// ---------------------------------------------------------------------------
__global__ void verify_kernel(int BALL) {
    int row = blockIdx.x * blockDim.x + threadIdx.x;
    if (row >= BALL) return;
    int cnt = g_cnt[row];
    float A = unford(g_bestu[row]);
    if (cnt == 0 || cnt > CAP || A < T0) {
        int slot = atomicAdd(&g_nflag, 1);
        if (slot < MAXFLAG) { g_flaglist[slot] = row; g_fbkey[slot] = 0ull; }
    }
}

// ---------------------------------------------------------------------------
// 5) exact fp32 rescoring of candidates (one warp per row)
// ---------------------------------------------------------------------------
__global__ __launch_bounds__(256) void rescore_kernel(const float* __restrict__ queue) {
    int lane = threadIdx.x & 31, wid = threadIdx.x >> 5;
    int row = blockIdx.x * 8 + wid;
    int cnt = g_cnt[row];
    if (cnt > CAP) cnt = CAP;
    if (cnt == 0) { if (lane == 0) g_idx[row] = 0; return; }  // fallback covers
    float4 p = ((const float4*)(g_P + (size_t)row * D))[lane];
    unsigned long long bkey = 0ull;
    for (int i = 0; i < cnt; i++) {
        int col = g_cand[row * CAP + i];
        float4 q = ((const float4*)(queue + (size_t)col * D))[lane];
        float d = fmaf(p.x, q.x, fmaf(p.y, q.y, fmaf(p.z, q.z, p.w * q.w)));
#pragma unroll
        for (int off = 16; off > 0; off >>= 1)
            d += __shfl_xor_sync(0xffffffffu, d, off);
        unsigned long long key =
            ((unsigned long long)ford(d) << 32) |
            (unsigned long long)(0xFFFFFFFFu - (unsigned)col);
        if (key > bkey) bkey = key;
    }
    if (lane == 0)
        g_idx[row] = (int)(0xFFFFFFFFu - (unsigned)(bkey & 0xFFFFFFFFull));
}

// ---------------------------------------------------------------------------
// 6) exact fp32 full-scan fallback for flagged rows
// ---------------------------------------------------------------------------
__global__ __launch_bounds__(256, 1)
void fallback_kernel(const float* __restrict__ queue) {
    int nf = g_nflag;
    if (nf == 0) return;
    if (nf > MAXFLAG) nf = MAXFLAG;

    extern __shared__ float fsm[];
    __shared__ unsigned long long skey[MAXFLAG];
    for (int i = threadIdx.x; i < nf * 128; i += 256)
        fsm[i] = g_P[(size_t)g_flaglist[i >> 7] * D + (i & 127)];
    for (int i = threadIdx.x; i < nf; i += 256) skey[i] = 0ull;
    __syncthreads();

    int q = blockIdx.x * 256 + threadIdx.x;
    float4 qr[32];
    const float4* qp = (const float4*)(queue + (size_t)q * D);
#pragma unroll
    for (int i = 0; i < 32; i++) qr[i] = qp[i];

    for (int f = 0; f < nf; f++) {
        const float4* pr = (const float4*)(fsm + f * 128);
        float s0 = 0.f, s1 = 0.f, s2 = 0.f, s3 = 0.f;
#pragma unroll
        for (int i = 0; i < 32; i++) {
            float4 p = pr[i];
            s0 = fmaf(qr[i].x, p.x, s0);
            s1 = fmaf(qr[i].y, p.y, s1);
            s2 = fmaf(qr[i].z, p.z, s2);
            s3 = fmaf(qr[i].w, p.w, s3);
        }
        float dot = (s0 + s1) + (s2 + s3);
        unsigned long long key =
            ((unsigned long long)ford(dot) << 32) |
            (unsigned long long)(0xFFFFFFFFu - (unsigned)q);
#pragma unroll
        for (int off = 16; off > 0; off >>= 1) {
            unsigned long long o = __shfl_xor_sync(0xffffffffu, key, off);
            if (o > key) key = o;
        }
        if ((threadIdx.x & 31) == 0) atomicMax(&skey[f], key);
    }
    __syncthreads();
    for (int f = threadIdx.x; f < nf; f += 256)
        atomicMax(&g_fbkey[f], skey[f]);
}

__global__ void fixup_kernel() {
    int nf = g_nflag;
    if (nf > MAXFLAG) nf = MAXFLAG;
    int s = threadIdx.x;
    if (s < nf)
        g_idx[g_flaglist[s]] =
            (int)(0xFFFFFFFFu - (unsigned)(g_fbkey[s] & 0xFFFFFFFFull));
}

// ---------------------------------------------------------------------------
// 7) gather NN rows
// ---------------------------------------------------------------------------
__global__ void gather_kernel(const float* __restrict__ queue) {
    int row = blockIdx.x, l = threadIdx.x;
    unsigned idx = (unsigned)g_idx[row];
    if (idx >= 65536u) idx = 0u;
    ((float4*)g_NN)[(size_t)row * 32 + l] =
        ((const float4*)queue)[(size_t)idx * 32 + l];
}

// ---------------------------------------------------------------------------
// fp32 register-tile GEMM for logits
// ---------------------------------------------------------------------------
__device__ __forceinline__ void load_tile_sw(const float* __restrict__ src,
                                             float* sm, int tid) {
    int w = tid >> 5, l = tid & 31;
#pragma unroll
    for (int m = 0; m < 16; m++) {
        int r = w + m * 8;
        float4 v = *(const float4*)(src + (size_t)r * D + 4 * l);
        int slot = (((r >> 2) ^ l) << 2) + (r & 3);
        sm[(4 * l + 0) * 128 + slot] = v.x;
        sm[(4 * l + 1) * 128 + slot] = v.y;
        sm[(4 * l + 2) * 128 + slot] = v.z;
        sm[(4 * l + 3) * 128 + slot] = v.w;
    }
}

__device__ __forceinline__ void mm_tile(const float* sp, const float* sq,
                                        int tx, int ty, float c[8][8]) {
    const float4* sp4 = (const float4*)sp;
    const float4* sq4 = (const float4*)sq;
#pragma unroll 4
    for (int k = 0; k < 128; k++) {
        int s = (k >> 2) & 31;
        float4 A0 = sp4[k * 32 + (ty ^ s)];
        float4 A1 = sp4[k * 32 + ((ty + 16) ^ s)];
        float4 B0 = sq4[k * 32 + (tx ^ s)];
        float4 B1 = sq4[k * 32 + ((tx + 16) ^ s)];
        float a[8] = {A0.x, A0.y, A0.z, A0.w, A1.x, A1.y, A1.z, A1.w};
        float b[8] = {B0.x, B0.y, B0.z, B0.w, B1.x, B1.y, B1.z, B1.w};
#pragma unroll
        for (int i = 0; i < 8; i++)
#pragma unroll
            for (int j = 0; j < 8; j++)
                c[i][j] = fmaf(a[i], b[j], c[i][j]);
    }
}

__global__ __launch_bounds__(256) void gemm_logits_kernel(int B, float invT) {
    extern __shared__ float smemf[];
    float* sp = smemf;
    float* sq = smemf + 128 * 128;
    int tid = threadIdx.x, tx = tid & 15, ty = tid >> 4;
    int z = blockIdx.z;

    const float* A = g_NN + (size_t)(z * B + blockIdx.x * 128) * D;
    const float* Bm = g_P + (size_t)((z ? 0 : B) + blockIdx.y * 128) * D;

    load_tile_sw(A, sp, tid);
    load_tile_sw(Bm, sq, tid);
    __syncthreads();

    float c[8][8];
#pragma unroll
    for (int i = 0; i < 8; i++)
#pragma unroll
        for (int j = 0; j < 8; j++) c[i][j] = 0.f;

    mm_tile(sp, sq, tx, ty, c);

    int rowA0 = blockIdx.x * 128, colB0 = blockIdx.y * 128;
    float* Ld = g_logits + (size_t)(2 * B * z) * B;
    float* Lt = g_logits + (size_t)(2 * B * z + B) * B;

#pragma unroll
    for (int i = 0; i < 8; i++) {
        int rA = rowA0 + ((i < 4) ? (4 * ty + i) : (64 + 4 * ty + i - 4));
        float4 v0 = make_float4(c[i][0] * invT, c[i][1] * invT,
                                c[i][2] * invT, c[i][3] * invT);
        float4 v1 = make_float4(c[i][4] * invT, c[i][5] * invT,
                                c[i][6] * invT, c[i][7] * invT);
        *(float4*)(Ld + (size_t)rA * B + colB0 + 4 * tx) = v0;
        *(float4*)(Ld + (size_t)rA * B + colB0 + 64 + 4 * tx) = v1;
    }
#pragma unroll
    for (int j = 0; j < 8; j++) {
        int cB = colB0 + ((j < 4) ? (4 * tx + j) : (64 + 4 * tx + j - 4));
        float4 t0 = make_float4(c[0][j] * invT, c[1][j] * invT,
                                c[2][j] * invT, c[3][j] * invT);
        float4 t1 = make_float4(c[4][j] * invT, c[5][j] * invT,
                                c[6][j] * invT, c[7][j] * invT);
        *(float4*)(Lt + (size_t)cB * B + rowA0 + 4 * ty) = t0;
        *(float4*)(Lt + (size_t)cB * B + rowA0 + 64 + 4 * ty) = t1;
    }
}

// ---------------------------------------------------------------------------
// 8) per-row log-softmax loss
// ---------------------------------------------------------------------------
__global__ void lse_loss_kernel(float* __restrict__ out, int B) {
    int row = blockIdx.x;
    const float* r = g_logits + (size_t)row * B;
    float m = -1e30f, s = 0.f;
    for (int t = threadIdx.x; t < B; t += blockDim.x) {
        float v = r[t];
        if (v > m) { s = s * __expf(m - v) + 1.f; m = v; }
        else       { s += __expf(v - m); }
    }
    unsigned lane = threadIdx.x & 31, w = threadIdx.x >> 5;
#pragma unroll
    for (int off = 16; off > 0; off >>= 1) {
        float om = __shfl_down_sync(0xffffffffu, m, off);
        float os = __shfl_down_sync(0xffffffffu, s, off);
        float nm = fmaxf(m, om);
        s = s * __expf(m - nm) + os * __expf(om - nm);
        m = nm;
    }
    __shared__ float shm[8], shs[8];
    if (lane == 0) { shm[w] = m; shs[w] = s; }
    __syncthreads();
    if (threadIdx.x == 0) {
        m = shm[0]; s = shs[0];
#pragma unroll
        for (int k = 1; k < 8; k++) {
            float nm = fmaxf(m, shm[k]);
            s = s * __expf(m - nm) + shs[k] * __expf(shm[k] - nm);
            m = nm;
        }
        out[row] = (m + logf(s)) - r[row % B];
    }
}

// ---------------------------------------------------------------------------
extern "C" void kernel_launch(void* const* d_in, const int* in_sizes, int n_in,
                              void* d_out, int out_size) {
    const float* p1 = (const float*)d_in[0];
    const float* p2 = (const float*)d_in[1];
    const float* queue = (const float*)d_in[2];
    int B = in_sizes[0] / D;     // 2048
    int Q = in_sizes[2] / D;     // 65536
    int BALL = 2 * B;
    float* out = (float*)d_out;

    cudaFuncSetAttribute(nn_kernel,
                         cudaFuncAttributeMaxDynamicSharedMemorySize, SMEM_NN);
    cudaFuncSetAttribute(fallback_kernel,
                         cudaFuncAttributeMaxDynamicSharedMemorySize, 65536);
    cudaFuncSetAttribute(gemm_logits_kernel,
                         cudaFuncAttributeMaxDynamicSharedMemorySize, 131072);

    init_kernel<<<16, 256>>>();
    normalize_kernel<<<BALL, 32>>>(p1, p2, B);
    convq_kernel<<<(Q * D / 4) / 256, 256>>>(queue);

    int rps = Q / NSPLIT;
    nn_kernel<<<dim3(BALL / 128, NSPLIT), 256, SMEM_NN>>>(rps);

    verify_kernel<<<(BALL + 255) / 256, 256>>>(BALL);
    rescore_kernel<<<BALL / 8, 256>>>(queue);
    fallback_kernel<<<Q / 256, 256, 65536>>>(queue);
    fixup_kernel<<<1, MAXFLAG>>>();
    gather_kernel<<<BALL, 32>>>(queue);

    gemm_logits_kernel<<<dim3(B / 128, B / 128, 2), 256, 131072>>>(B, 10.0f);

    lse_loss_kernel<<<4 * B, 256>>>(out, B);
}

// round 5
// speedup vs baseline: 2.9492x; 1.0875x over previous
#include <cuda_runtime.h>
#include <cuda_bf16.h>
#include <math.h>

#define D 128
#define NSPLIT 8
#define CAP 128
#define MAXFLAG 128
#define T0 0.30f
#define DELTA 0.0165f

// ---- static scratch ----
__device__ float g_P[4096 * 128];
__device__ __nv_bfloat16 g_Ah[4096 * 128];
__device__ __nv_bfloat16 g_Qh[65536 * 128];
__device__ float g_NN[4096 * 128];
__device__ int      g_cand[4096 * CAP];
__device__ int      g_cnt[4096];
__device__ unsigned g_bestu[4096];
__device__ int   g_idx[4096];
__device__ int   g_nflag;
__device__ int   g_flaglist[MAXFLAG];
__device__ unsigned long long g_fbkey[MAXFLAG];
__device__ float g_logits[8192 * 2048];

// swizzled bf16 tile addressing: rows x 128 cols, 256B/row, 16B chunks
#define TSW(r, c) (((r) * 256) + ((((c) ^ ((r) & 7))) << 4))

__device__ __forceinline__ unsigned smem_u32(const void* p) {
    unsigned a;
    asm("{ .reg .u64 t; cvta.to.shared.u64 t, %1; cvt.u32.u64 %0, t; }"
        : "=r"(a) : "l"(p));
    return a;
}
__device__ __forceinline__ void cp_async16(unsigned sm, const void* g) {
    asm volatile("cp.async.cg.shared.global [%0], [%1], 16;" :: "r"(sm), "l"(g));
}
__device__ __forceinline__ void cp_commit() {
    asm volatile("cp.async.commit_group;");
}
__device__ __forceinline__ void ldsm4(unsigned& r0, unsigned& r1, unsigned& r2,
                                      unsigned& r3, unsigned addr) {
    asm volatile("ldmatrix.sync.aligned.m8n8.x4.shared.b16 {%0,%1,%2,%3}, [%4];"
                 : "=r"(r0), "=r"(r1), "=r"(r2), "=r"(r3) : "r"(addr));
}
__device__ __forceinline__ void mma16816(float c[4], const unsigned a[4],
                                         unsigned b0, unsigned b1) {
    asm volatile("mma.sync.aligned.m16n8k16.row.col.f32.bf16.bf16.f32 "
                 "{%0,%1,%2,%3}, {%4,%5,%6,%7}, {%8,%9}, {%0,%1,%2,%3};"
                 : "+f"(c[0]), "+f"(c[1]), "+f"(c[2]), "+f"(c[3])
                 : "r"(a[0]), "r"(a[1]), "r"(a[2]), "r"(a[3]), "r"(b0), "r"(b1));
}
__device__ __forceinline__ unsigned ford(float f) {
    unsigned u = __float_as_uint(f);
    return (u & 0x80000000u) ? ~u : (u | 0x80000000u);
}
__device__ __forceinline__ float unford(unsigned k) {
    unsigned u = (k & 0x80000000u) ? (k ^ 0x80000000u) : ~k;
    return __uint_as_float(u);
}

// ---------------------------------------------------------------------------
// 0) re-init per-call state (graph-replay determinism)
// ---------------------------------------------------------------------------
__global__ void init_kernel() {
    int i = blockIdx.x * blockDim.x + threadIdx.x;
    if (i < 4096) { g_cnt[i] = 0; g_bestu[i] = 0u; }
    if (i == 0) g_nflag = 0;
}

// ---------------------------------------------------------------------------
// 1) normalize -> g_P fp32 + g_Ah bf16(hi)
// ---------------------------------------------------------------------------
__global__ void normalize_kernel(const float* __restrict__ p1,
                                 const float* __restrict__ p2, int B) {
    int row = blockIdx.x, l = threadIdx.x;
    const float* src = (row < B) ? (p1 + (size_t)row * D)
                                 : (p2 + (size_t)(row - B) * D);
    float4 v = ((const float4*)src)[l];
    float ss = v.x * v.x + v.y * v.y + v.z * v.z + v.w * v.w;
#pragma unroll
    for (int off = 16; off > 0; off >>= 1)
        ss += __shfl_xor_sync(0xffffffffu, ss, off);
    float inv = 1.0f / sqrtf(ss);
    float4 o = make_float4(v.x * inv, v.y * inv, v.z * inv, v.w * inv);
    ((float4*)g_P)[(size_t)row * 32 + l] = o;
    __nv_bfloat16 hi[4] = {__float2bfloat16(o.x), __float2bfloat16(o.y),
                           __float2bfloat16(o.z), __float2bfloat16(o.w)};
    *(uint2*)(g_Ah + (size_t)row * D + 4 * l) = *(uint2*)hi;
}

// ---------------------------------------------------------------------------
// 2) queue -> bf16 hi
// ---------------------------------------------------------------------------
__global__ void convq_kernel(const float* __restrict__ queue) {
    int i = blockIdx.x * blockDim.x + threadIdx.x;
    float4 v = ((const float4*)queue)[i];
    __nv_bfloat16 hi[4] = {__float2bfloat16(v.x), __float2bfloat16(v.y),
                           __float2bfloat16(v.z), __float2bfloat16(v.w)};
    *(uint2*)(g_Qh + 4 * (size_t)i) = *(uint2*)hi;
}

// ---------------------------------------------------------------------------
// 3) NN screen: 1-term bf16 HMMA, M=64 CTA tile, 2 CTAs/SM
// ---------------------------------------------------------------------------
#define OFF_AH 0
#define OFF_B  16384                    // 2 buffers x 32KB
#define SMEM_NN (16384 + 2 * 32768)     // 81920

__global__ __launch_bounds__(256, 2)
void nn_kernel(int rps) {
    extern __shared__ char smem[];
    unsigned sb = smem_u32(smem);
    int tid = threadIdx.x, lane = tid & 31, wid = tid >> 5;
    int wm = wid >> 2, wn = wid & 3;    // 2 x 4 warp grid
    int rowbase = blockIdx.x * 64;
    int q0 = blockIdx.y * rps;
    int nch = rps >> 7;

    // A (hi, 64 rows) -> swizzled smem: 4 threads/row, 4 16B chunks each
    {
        int r = tid >> 2, qid = tid & 3;
        const uint4* sh = (const uint4*)(g_Ah + (size_t)(rowbase + r) * D);
#pragma unroll
        for (int i = 0; i < 4; i++) {
            int c = 4 * qid + i;
            *(uint4*)(smem + OFF_AH + TSW(r, c)) = sh[c];
        }
    }

    int brow = tid >> 1, bh = tid & 1;
    auto issueB = [&](int ch) {
        unsigned bdst = sb + OFF_B + (unsigned)(ch & 1) * 32768u;
        const __nv_bfloat16* qh = g_Qh + (size_t)(q0 + ch * 128 + brow) * D;
#pragma unroll
        for (int i = 0; i < 8; i++) {
            int c = 8 * bh + i;
            cp_async16(bdst + TSW(brow, c), qh + c * 8);
        }
        cp_commit();
    };
    issueB(0);

    float best[4];
#pragma unroll
    for (int s = 0; s < 4; s++) best[s] = -INFINITY;

    int a_r = ((lane >> 3) & 1) * 8 + (lane & 7);
    int a_cq = lane >> 4;
    int b_r = ((lane >> 4) << 3) + (lane & 7);
    int b_cq = (lane >> 3) & 1;

    for (int ch = 0; ch < nch; ch++) {
        if (ch + 1 < nch) {
            issueB(ch + 1);
            asm volatile("cp.async.wait_group 1;");
        } else {
            asm volatile("cp.async.wait_group 0;");
        }
        __syncthreads();

        unsigned bhb = sb + OFF_B + (unsigned)(ch & 1) * 32768u;

        float acc[2][4][4];
#pragma unroll
        for (int mt = 0; mt < 2; mt++)
#pragma unroll
            for (int nt = 0; nt < 4; nt++)
#pragma unroll
                for (int e = 0; e < 4; e++) acc[mt][nt][e] = 0.f;

#pragma unroll
        for (int ks = 0; ks < 8; ks++) {
            int c0 = 2 * ks;
            unsigned bf[8];
#pragma unroll
            for (int nt2 = 0; nt2 < 2; nt2++) {
                int n = wn * 32 + nt2 * 16 + b_r;
                ldsm4(bf[4 * nt2], bf[4 * nt2 + 1], bf[4 * nt2 + 2],
                      bf[4 * nt2 + 3], bhb + TSW(n, c0 + b_cq));
            }
            unsigned af[2][4];
#pragma unroll
            for (int mt = 0; mt < 2; mt++) {
                int r = wm * 32 + mt * 16 + a_r;
                ldsm4(af[mt][0], af[mt][1], af[mt][2], af[mt][3],
                      sb + OFF_AH + TSW(r, c0 + a_cq));
            }
#pragma unroll
            for (int mt = 0; mt < 2; mt++)
#pragma unroll
                for (int nt = 0; nt < 4; nt++)
                    mma16816(acc[mt][nt], af[mt],
                             bf[(nt >> 1) * 4 + (nt & 1) * 2],
                             bf[(nt >> 1) * 4 + (nt & 1) * 2 + 1]);
        }
        __syncthreads();

        // epilogue: best tracking + provable candidate collection
        int qb = q0 + ch * 128 + wn * 32 + 2 * (lane & 3);
#pragma unroll
        for (int mt = 0; mt < 2; mt++)
#pragma unroll
            for (int p = 0; p < 2; p++) {
                int s = mt * 2 + p;
                int row = rowbase + wm * 32 + mt * 16 + p * 8 + (lane >> 2);
                float thr = fmaxf(best[s], T0) - DELTA;
#pragma unroll
                for (int nt = 0; nt < 4; nt++)
#pragma unroll
                    for (int e = 0; e < 2; e++) {
                        float v = acc[mt][nt][p * 2 + e];
                        if (v > best[s]) best[s] = v;
                        if (v > thr) {
                            int col = qb + nt * 8 + e;
                            int slot = atomicAdd(&g_cnt[row], 1);
                            if (slot < CAP) g_cand[row * CAP + slot] = col;
                        }
                    }
            }
    }

    // per-row approx max -> g_bestu
#pragma unroll
    for (int s = 0; s < 4; s++) {
        float b = best[s];
#pragma unroll
        for (int off = 1; off <= 2; off <<= 1)
            b = fmaxf(b, __shfl_xor_sync(0xffffffffu, b, off));
        if ((lane & 3) == 0) {
            int row = rowbase + wm * 32 + (s >> 1) * 16 + (s & 1) * 8 + (lane >> 2);
            atomicMax(&g_bestu[row], ford(b));
        }
    }
}

// ---------------------------------------------------------------------------
// 4) verify: flag rows where the collection guarantee doesn't hold
// ---------------------------------------------------------------------------
__global__ void verify_kernel(int BALL) {
    int row = blockIdx.x * blockDim.x + threadIdx.x;
    if (row >= BALL) return;
    int cnt = g_cnt[row];
    float A = unford(g_bestu[row]);
    if (cnt == 0 || cnt > CAP || A < T0) {
        int slot = atomicAdd(&g_nflag, 1);
        if (slot < MAXFLAG) { g_flaglist[slot] = row; g_fbkey[slot] = 0ull; }
    }
}

// ---------------------------------------------------------------------------
// 5) exact fp32 rescoring of candidates (one warp per row)
// ---------------------------------------------------------------------------
__global__ __launch_bounds__(256) void rescore_kernel(const float* __restrict__ queue) {
    int lane = threadIdx.x & 31, wid = threadIdx.x >> 5;
    int row = blockIdx.x * 8 + wid;
    int cnt = g_cnt[row];
    if (cnt > CAP) cnt = CAP;
    if (cnt == 0) { if (lane == 0) g_idx[row] = 0; return; }  // fallback covers
    float4 p = ((const float4*)(g_P + (size_t)row * D))[lane];
    unsigned long long bkey = 0ull;
    for (int i = 0; i < cnt; i++) {
        int col = g_cand[row * CAP + i];
        float4 q = ((const float4*)(queue + (size_t)col * D))[lane];
        float d = fmaf(p.x, q.x, fmaf(p.y, q.y, fmaf(p.z, q.z, p.w * q.w)));
#pragma unroll
        for (int off = 16; off > 0; off >>= 1)
            d += __shfl_xor_sync(0xffffffffu, d, off);
        unsigned long long key =
            ((unsigned long long)ford(d) << 32) |
            (unsigned long long)(0xFFFFFFFFu - (unsigned)col);
        if (key > bkey) bkey = key;
    }
    if (lane == 0)
        g_idx[row] = (int)(0xFFFFFFFFu - (unsigned)(bkey & 0xFFFFFFFFull));
}

// ---------------------------------------------------------------------------
// 6) exact fp32 full-scan fallback for flagged rows
// ---------------------------------------------------------------------------
__global__ __launch_bounds__(256, 1)
void fallback_kernel(const float* __restrict__ queue) {
    int nf = g_nflag;
    if (nf == 0) return;
    if (nf > MAXFLAG) nf = MAXFLAG;

    extern __shared__ float fsm[];
    __shared__ unsigned long long skey[MAXFLAG];
    for (int i = threadIdx.x; i < nf * 128; i += 256)
        fsm[i] = g_P[(size_t)g_flaglist[i >> 7] * D + (i & 127)];
    for (int i = threadIdx.x; i < nf; i += 256) skey[i] = 0ull;
    __syncthreads();

    int q = blockIdx.x * 256 + threadIdx.x;
    float4 qr[32];
    const float4* qp = (const float4*)(queue + (size_t)q * D);
#pragma unroll
    for (int i = 0; i < 32; i++) qr[i] = qp[i];

    for (int f = 0; f < nf; f++) {
        const float4* pr = (const float4*)(fsm + f * 128);
        float s0 = 0.f, s1 = 0.f, s2 = 0.f, s3 = 0.f;
#pragma unroll
        for (int i = 0; i < 32; i++) {
            float4 p = pr[i];
            s0 = fmaf(qr[i].x, p.x, s0);
            s1 = fmaf(qr[i].y, p.y, s1);
            s2 = fmaf(qr[i].z, p.z, s2);
            s3 = fmaf(qr[i].w, p.w, s3);
        }
        float dot = (s0 + s1) + (s2 + s3);
        unsigned long long key =
            ((unsigned long long)ford(dot) << 32) |
            (unsigned long long)(0xFFFFFFFFu - (unsigned)q);
#pragma unroll
        for (int off = 16; off > 0; off >>= 1) {
            unsigned long long o = __shfl_xor_sync(0xffffffffu, key, off);
            if (o > key) key = o;
        }
        if ((threadIdx.x & 31) == 0) atomicMax(&skey[f], key);
    }
    __syncthreads();
    for (int f = threadIdx.x; f < nf; f += 256)
        atomicMax(&g_fbkey[f], skey[f]);
}

__global__ void fixup_kernel() {
    int nf = g_nflag;
    if (nf > MAXFLAG) nf = MAXFLAG;
    int s = threadIdx.x;
    if (s < nf)
        g_idx[g_flaglist[s]] =
            (int)(0xFFFFFFFFu - (unsigned)(g_fbkey[s] & 0xFFFFFFFFull));
}

// ---------------------------------------------------------------------------
// 7) gather NN rows
// ---------------------------------------------------------------------------
__global__ void gather_kernel(const float* __restrict__ queue) {
    int row = blockIdx.x, l = threadIdx.x;
    unsigned idx = (unsigned)g_idx[row];
    if (idx >= 65536u) idx = 0u;
    ((float4*)g_NN)[(size_t)row * 32 + l] =
        ((const float4*)queue)[(size_t)idx * 32 + l];
}

// ---------------------------------------------------------------------------
// fp32 register-tile GEMM for logits
// ---------------------------------------------------------------------------
__device__ __forceinline__ void load_tile_sw(const float* __restrict__ src,
                                             float* sm, int tid) {
    int w = tid >> 5, l = tid & 31;
#pragma unroll
    for (int m = 0; m < 16; m++) {
        int r = w + m * 8;
        float4 v = *(const float4*)(src + (size_t)r * D + 4 * l);
        int slot = (((r >> 2) ^ l) << 2) + (r & 3);
        sm[(4 * l + 0) * 128 + slot] = v.x;
        sm[(4 * l + 1) * 128 + slot] = v.y;
        sm[(4 * l + 2) * 128 + slot] = v.z;
        sm[(4 * l + 3) * 128 + slot] = v.w;
    }
}

__device__ __forceinline__ void mm_tile(const float* sp, const float* sq,
                                        int tx, int ty, float c[8][8]) {
    const float4* sp4 = (const float4*)sp;
    const float4* sq4 = (const float4*)sq;
#pragma unroll 4
    for (int k = 0; k < 128; k++) {
        int s = (k >> 2) & 31;
        float4 A0 = sp4[k * 32 + (ty ^ s)];
        float4 A1 = sp4[k * 32 + ((ty + 16) ^ s)];
        float4 B0 = sq4[k * 32 + (tx ^ s)];
        float4 B1 = sq4[k * 32 + ((tx + 16) ^ s)];
        float a[8] = {A0.x, A0.y, A0.z, A0.w, A1.x, A1.y, A1.z, A1.w};
        float b[8] = {B0.x, B0.y, B0.z, B0.w, B1.x, B1.y, B1.z, B1.w};
#pragma unroll
        for (int i = 0; i < 8; i++)
#pragma unroll
            for (int j = 0; j < 8; j++)
                c[i][j] = fmaf(a[i], b[j], c[i][j]);
    }
}

__global__ __launch_bounds__(256) void gemm_logits_kernel(int B, float invT) {
    extern __shared__ float smemf[];
    float* sp = smemf;
    float* sq = smemf + 128 * 128;
    int tid = threadIdx.x, tx = tid & 15, ty = tid >> 4;
    int z = blockIdx.z;

    const float* A = g_NN + (size_t)(z * B + blockIdx.x * 128) * D;
    const float* Bm = g_P + (size_t)((z ? 0 : B) + blockIdx.y * 128) * D;

    load_tile_sw(A, sp, tid);
    load_tile_sw(Bm, sq, tid);
    __syncthreads();

    float c[8][8];
#pragma unroll
    for (int i = 0; i < 8; i++)
#pragma unroll
        for (int j = 0; j < 8; j++) c[i][j] = 0.f;

    mm_tile(sp, sq, tx, ty, c);

    int rowA0 = blockIdx.x * 128, colB0 = blockIdx.y * 128;
    float* Ld = g_logits + (size_t)(2 * B * z) * B;
    float* Lt = g_logits + (size_t)(2 * B * z + B) * B;

#pragma unroll
    for (int i = 0; i < 8; i++) {
        int rA = rowA0 + ((i < 4) ? (4 * ty + i) : (64 + 4 * ty + i - 4));
        float4 v0 = make_float4(c[i][0] * invT, c[i][1] * invT,
                                c[i][2] * invT, c[i][3] * invT);
        float4 v1 = make_float4(c[i][4] * invT, c[i][5] * invT,
                                c[i][6] * invT, c[i][7] * invT);
        *(float4*)(Ld + (size_t)rA * B + colB0 + 4 * tx) = v0;
        *(float4*)(Ld + (size_t)rA * B + colB0 + 64 + 4 * tx) = v1;
    }
#pragma unroll
    for (int j = 0; j < 8; j++) {
        int cB = colB0 + ((j < 4) ? (4 * tx + j) : (64 + 4 * tx + j - 4));
        float4 t0 = make_float4(c[0][j] * invT, c[1][j] * invT,
                                c[2][j] * invT, c[3][j] * invT);
        float4 t1 = make_float4(c[4][j] * invT, c[5][j] * invT,
                                c[6][j] * invT, c[7][j] * invT);
        *(float4*)(Lt + (size_t)cB * B + rowA0 + 4 * ty) = t0;
        *(float4*)(Lt + (size_t)cB * B + rowA0 + 64 + 4 * ty) = t1;
    }
}

// ---------------------------------------------------------------------------
// 8) per-row log-softmax loss
// ---------------------------------------------------------------------------
__global__ void lse_loss_kernel(float* __restrict__ out, int B) {
    int row = blockIdx.x;
    const float* r = g_logits + (size_t)row * B;
    float m = -1e30f, s = 0.f;
    for (int t = threadIdx.x; t < B; t += blockDim.x) {
        float v = r[t];
        if (v > m) { s = s * __expf(m - v) + 1.f; m = v; }
        else       { s += __expf(v - m); }
    }
    unsigned lane = threadIdx.x & 31, w = threadIdx.x >> 5;
#pragma unroll
    for (int off = 16; off > 0; off >>= 1) {
        float om = __shfl_down_sync(0xffffffffu, m, off);
        float os = __shfl_down_sync(0xffffffffu, s, off);
        float nm = fmaxf(m, om);
        s = s * __expf(m - nm) + os * __expf(om - nm);
        m = nm;
    }
    __shared__ float shm[8], shs[8];
    if (lane == 0) { shm[w] = m; shs[w] = s; }
    __syncthreads();
    if (threadIdx.x == 0) {
        m = shm[0]; s = shs[0];
#pragma unroll
        for (int k = 1; k < 8; k++) {
            float nm = fmaxf(m, shm[k]);
            s = s * __expf(m - nm) + shs[k] * __expf(shm[k] - nm);
            m = nm;
        }
        out[row] = (m + logf(s)) - r[row % B];
    }
}

// ---------------------------------------------------------------------------
extern "C" void kernel_launch(void* const* d_in, const int* in_sizes, int n_in,
                              void* d_out, int out_size) {
    const float* p1 = (const float*)d_in[0];
    const float* p2 = (const float*)d_in[1];
    const float* queue = (const float*)d_in[2];
    int B = in_sizes[0] / D;     // 2048
    int Q = in_sizes[2] / D;     // 65536
    int BALL = 2 * B;
    float* out = (float*)d_out;

    cudaFuncSetAttribute(nn_kernel,
                         cudaFuncAttributeMaxDynamicSharedMemorySize, SMEM_NN);
    cudaFuncSetAttribute(fallback_kernel,
                         cudaFuncAttributeMaxDynamicSharedMemorySize, 65536);
    cudaFuncSetAttribute(gemm_logits_kernel,
                         cudaFuncAttributeMaxDynamicSharedMemorySize, 131072);

    init_kernel<<<16, 256>>>();
    normalize_kernel<<<BALL, 32>>>(p1, p2, B);
    convq_kernel<<<(Q * D / 4) / 256, 256>>>(queue);

    int rps = Q / NSPLIT;
    nn_kernel<<<dim3(BALL / 64, NSPLIT), 256, SMEM_NN>>>(rps);

    verify_kernel<<<(BALL + 255) / 256, 256>>>(BALL);
    rescore_kernel<<<BALL / 8, 256>>>(queue);
    fallback_kernel<<<Q / 256, 256, 65536>>>(queue);
    fixup_kernel<<<1, MAXFLAG>>>();
    gather_kernel<<<BALL, 32>>>(queue);

    gemm_logits_kernel<<<dim3(B / 128, B / 128, 2), 256, 131072>>>(B, 10.0f);

    lse_loss_kernel<<<4 * B, 256>>>(out, B);
}